// round 4
// baseline (speedup 1.0000x reference)
#include <cuda_runtime.h>

#define NMAX 200704
#define SB 1024   // stats partial blocks

__device__ float g_part[SB * 128];
__device__ float g_scale[64];
__device__ float g_shift[64];
__device__ float g_cat[(size_t)NMAX * 64];   // [N][64]: skip || upsampled
__device__ float g_c1[(size_t)NMAX * 64];    // [M][64]
__device__ float g_c2[(size_t)NMAX * 64];    // [M][64]

// ---------------------------------------------------------------------------
// Batch stats: float4 lanes, deterministic two-stage reduction.
// ---------------------------------------------------------------------------
__global__ void __launch_bounds__(256)
stats4(const float* __restrict__ x, int n, int C, int ld) {
    __shared__ float4 sm[512];
    const int tid = threadIdx.x;
    const int V = C / 4;
    const int rpi = 256 / V;
    const int c4 = tid % V;
    const int rg = tid / V;
    float4 s = {0.f, 0.f, 0.f, 0.f}, q = {0.f, 0.f, 0.f, 0.f};
    for (int r = blockIdx.x * rpi + rg; r < n; r += gridDim.x * rpi) {
        float4 v = *(const float4*)(x + (size_t)r * ld + 4 * c4);
        s.x += v.x; s.y += v.y; s.z += v.z; s.w += v.w;
        q.x += v.x * v.x; q.y += v.y * v.y; q.z += v.z * v.z; q.w += v.w * v.w;
    }
    sm[tid] = s;
    sm[256 + tid] = q;
    __syncthreads();
    if (rg == 0) {
        float4 ts = {0.f, 0.f, 0.f, 0.f}, tq = {0.f, 0.f, 0.f, 0.f};
        for (int j = 0; j < rpi; j++) {
            float4 a = sm[j * V + c4];
            ts.x += a.x; ts.y += a.y; ts.z += a.z; ts.w += a.w;
            float4 b = sm[256 + j * V + c4];
            tq.x += b.x; tq.y += b.y; tq.z += b.z; tq.w += b.w;
        }
        float* p = g_part + blockIdx.x * 128 + 4 * c4;
        p[0] = ts.x; p[1] = ts.y; p[2] = ts.z; p[3] = ts.w;
        p[64] = tq.x; p[65] = tq.y; p[66] = tq.z; p[67] = tq.w;
    }
}

__global__ void stats_final(int n, int C, const float* __restrict__ gg, const float* __restrict__ bb) {
    int c = threadIdx.x;
    if (c >= C) return;
    float s0 = 0.f, s1 = 0.f, s2 = 0.f, s3 = 0.f;
    float q0 = 0.f, q1 = 0.f, q2 = 0.f, q3 = 0.f;
    for (int b = 0; b < SB; b += 4) {
        s0 += g_part[(b + 0) * 128 + c];      q0 += g_part[(b + 0) * 128 + 64 + c];
        s1 += g_part[(b + 1) * 128 + c];      q1 += g_part[(b + 1) * 128 + 64 + c];
        s2 += g_part[(b + 2) * 128 + c];      q2 += g_part[(b + 2) * 128 + 64 + c];
        s3 += g_part[(b + 3) * 128 + c];      q3 += g_part[(b + 3) * 128 + 64 + c];
    }
    float s = (s0 + s1) + (s2 + s3);
    float q = (q0 + q1) + (q2 + q3);
    float inv_n = 1.f / (float)n;
    float mu = s * inv_n;
    float var = q * inv_n - mu * mu;
    float sc = gg[c] * rsqrtf(var + 1e-4f);
    g_scale[c] = sc;
    g_shift[c] = bb[c] - mu * sc;
}

// ---------------------------------------------------------------------------
// Tap-major, weight-stationary sparse conv, smem-broadcast x.
//   k outermost; warp holds W[k][ci][co-lane] in registers.
//   Gathered row is BN+ReLU'd, staged to a per-warp smem buffer (double slot),
//   then read back as float4 broadcasts (conflict-free) for the FMA loop.
//   Next pair's gather LDGs issue before the FMA loop (latency overlap).
//   Deterministic RMW: fixed warp owns each row stripe, fixed k order.
// ---------------------------------------------------------------------------
template <int K, int Cin, int Cout>
__global__ void __launch_bounds__(256, 2)
tapconv(const float* __restrict__ in, int ldin,
        const int* __restrict__ nbr,          // [K][M]
        const float* __restrict__ W,          // [K][Cin][Cout]
        float* __restrict__ out, int ldout, int outOff,
        int M, int P) {
    __shared__ float xb[8 * 2 * 64];          // 8 warps x 2 slots x Cin<=64

    const int tid = threadIdx.x;
    const int lane = tid & 31;
    const int w = tid >> 5;
    constexpr int HW = Cout / 32;     // warps per row stripe
    constexpr int NWP = 8 / HW;       // row stripes per block
    const int wp = w / HW;
    const int half = w % HW;
    const int coB = half * 32;

    const int range = (M + gridDim.x - 1) / gridDim.x;
    const int b0 = blockIdx.x * range;
    const int b1 = min(M, b0 + range);

    for (int i = tid; i < (b1 - b0) * Cout; i += 256) {
        int r = b0 + i / Cout, c = i % Cout;
        out[(size_t)r * ldout + outOff + c] = 0.f;
    }
    if (b0 >= b1) return;

    const float sc0 = g_scale[lane], sh0 = g_shift[lane];
    float sc1 = 0.f, sh1 = 0.f;
    if (Cin == 64) { sc1 = g_scale[lane + 32]; sh1 = g_shift[lane + 32]; }

    float* xw = xb + w * 2 * 64;

    for (int k = 0; k < K; k++) {
        float wreg[Cin];
        const float* Wk = W + (size_t)k * Cin * Cout;
#pragma unroll
        for (int ci = 0; ci < Cin; ci++) wreg[ci] = Wk[ci * Cout + coB + lane];
        const int* nk = nbr + (size_t)k * M;

        for (int rb = b0 + wp * 32; rb < b1; rb += NWP * 32) {
            const int r_l = rb + lane;
            int idxl = (r_l < b1) ? nk[r_l] : P;
            unsigned mask = __ballot_sync(0xffffffffu, idxl < P);
            if (!mask) continue;

            int t = __ffs(mask) - 1;
            int idx = __shfl_sync(0xffffffffu, idxl, t);
            float v0 = in[(size_t)idx * ldin + lane];
            float v1 = (Cin == 64) ? in[(size_t)idx * ldin + 32 + lane] : 0.f;
            int slot = 0;
            while (true) {
                mask &= mask - 1;
                int tn = 0; float p0 = 0.f, p1 = 0.f;
                if (mask) {                        // prefetch next pair
                    tn = __ffs(mask) - 1;
                    int idxn = __shfl_sync(0xffffffffu, idxl, tn);
                    p0 = in[(size_t)idxn * ldin + lane];
                    if (Cin == 64) p1 = in[(size_t)idxn * ldin + 32 + lane];
                }
                float* xs = xw + slot * 64;
                xs[lane] = fmaxf(fmaf(v0, sc0, sh0), 0.f);
                if (Cin == 64) xs[lane + 32] = fmaxf(fmaf(v1, sc1, sh1), 0.f);
                __syncwarp();

                const float4* xv = (const float4*)xs;
                float a0 = 0.f, a1 = 0.f, a2 = 0.f, a3 = 0.f;
#pragma unroll
                for (int i = 0; i < Cin / 4; i++) {
                    float4 x4 = xv[i];
                    a0 = fmaf(x4.x, wreg[4 * i + 0], a0);
                    a1 = fmaf(x4.y, wreg[4 * i + 1], a1);
                    a2 = fmaf(x4.z, wreg[4 * i + 2], a2);
                    a3 = fmaf(x4.w, wreg[4 * i + 3], a3);
                }
                const int r = rb + t;
                float* po = out + (size_t)r * ldout + outOff + coB + lane;
                *po += (a0 + a1) + (a2 + a3);
                if (!mask) break;
                t = tn; v0 = p0; v1 = p1; slot ^= 1;
            }
        }
    }
}

// ---------------------------------------------------------------------------
// Deconv (upsample, 1 tap per fine voxel): weights in smem, x staged via smem
// broadcast, 4-way accumulator ILP.
// ---------------------------------------------------------------------------
__global__ void __launch_bounds__(256)
deconv2(const float* __restrict__ in,          // [M][64]
        const int* __restrict__ up_cidx,       // [N]
        const int* __restrict__ up_k,          // [N]
        const float* __restrict__ W,           // [8][64][32]
        float* __restrict__ out,               // g_cat, cols 32:64
        int n) {
    extern __shared__ float Ws[];              // 8*64*32
    __shared__ float xb[8 * 2 * 64];
    for (int i = threadIdx.x; i < 8 * 2048; i += 256) Ws[i] = W[i];
    __syncthreads();

    const int lane = threadIdx.x & 31;
    const int w = threadIdx.x >> 5;
    const float sc0 = g_scale[lane], sh0 = g_shift[lane];
    const float sc1 = g_scale[lane + 32], sh1 = g_shift[lane + 32];
    float* xw = xb + w * 2 * 64;

    const int gw = blockIdx.x * 8 + w;
    const int stride = gridDim.x * 8;
    int slot = 0;
    int r = gw;
    float v0 = 0.f, v1 = 0.f;
    int k = 0;
    if (r < n) {
        int c = up_cidx[r];
        k = up_k[r];
        v0 = in[(size_t)c * 64 + lane];
        v1 = in[(size_t)c * 64 + 32 + lane];
    }
    while (r < n) {
        const int rn = r + stride;
        float p0 = 0.f, p1 = 0.f;
        int kn = 0;
        if (rn < n) {                           // prefetch next row
            int cn = up_cidx[rn];
            kn = up_k[rn];
            p0 = in[(size_t)cn * 64 + lane];
            p1 = in[(size_t)cn * 64 + 32 + lane];
        }
        float* xs = xw + slot * 64;
        xs[lane] = fmaxf(fmaf(v0, sc0, sh0), 0.f);
        xs[lane + 32] = fmaxf(fmaf(v1, sc1, sh1), 0.f);
        __syncwarp();

        const float* Wt = Ws + k * 2048;
        const float4* xv = (const float4*)xs;
        float a0 = 0.f, a1 = 0.f, a2 = 0.f, a3 = 0.f;
#pragma unroll
        for (int i = 0; i < 16; i++) {
            float4 x4 = xv[i];
            a0 = fmaf(x4.x, Wt[(4 * i + 0) * 32 + lane], a0);
            a1 = fmaf(x4.y, Wt[(4 * i + 1) * 32 + lane], a1);
            a2 = fmaf(x4.z, Wt[(4 * i + 2) * 32 + lane], a2);
            a3 = fmaf(x4.w, Wt[(4 * i + 3) * 32 + lane], a3);
        }
        out[(size_t)r * 64 + 32 + lane] = (a0 + a1) + (a2 + a3);
        r = rn; v0 = p0; v1 = p1; k = kn; slot ^= 1;
    }
}

// ---------------------------------------------------------------------------
extern "C" void kernel_launch(void* const* d_in, const int* in_sizes, int n_in,
                              void* d_out, int out_size) {
    (void)n_in; (void)out_size;
    const float* feat    = (const float*)d_in[0];
    const float* w_sub1  = (const float*)d_in[1];
    const float* w_down  = (const float*)d_in[2];
    const float* w_sub2  = (const float*)d_in[3];
    const float* w_up    = (const float*)d_in[4];
    const float* w_sub3  = (const float*)d_in[5];
    const float* g1 = (const float*)d_in[6],  *b1 = (const float*)d_in[7];
    const float* g2 = (const float*)d_in[8],  *b2 = (const float*)d_in[9];
    const float* g3 = (const float*)d_in[10], *b3 = (const float*)d_in[11];
    const float* g4 = (const float*)d_in[12], *b4 = (const float*)d_in[13];
    const float* g5 = (const float*)d_in[14], *b5 = (const float*)d_in[15];
    const int* nbr_fine   = (const int*)d_in[16];
    const int* nbr_coarse = (const int*)d_in[17];
    const int* down_idx   = (const int*)d_in[18];
    const int* up_cidx    = (const int*)d_in[19];
    const int* up_k       = (const int*)d_in[20];

    const int N = in_sizes[0] / 32;
    const int M = in_sizes[17] / 27;

    void* p;
    cudaGetSymbolAddress(&p, g_cat); float* cat = (float*)p;
    cudaGetSymbolAddress(&p, g_c1);  float* c1  = (float*)p;
    cudaGetSymbolAddress(&p, g_c2);  float* c2  = (float*)p;

    const int SMU = 8 * 64 * 32 * 4;   // 64KB dynamic (weights)
    cudaFuncSetAttribute(deconv2, cudaFuncAttributeMaxDynamicSharedMemorySize, SMU);

    const int GRID = 592;   // 256-thread blocks, 2/SM resident

    // BN1 -> sub1 (skip) into g_cat[:, 0:32]
    stats4<<<SB, 256>>>(feat, N, 32, 32);
    stats_final<<<1, 64>>>(N, 32, g1, b1);
    tapconv<27, 32, 32><<<GRID, 256>>>(feat, 32, nbr_fine, w_sub1, cat, 64, 0, N, N);

    // BN2 -> down conv (32->64)
    stats4<<<SB, 256>>>(cat, N, 32, 64);
    stats_final<<<1, 64>>>(N, 32, g2, b2);
    tapconv<8, 32, 64><<<GRID, 256>>>(cat, 64, down_idx, w_down, c1, 64, 0, M, N);

    // BN3 -> coarse submanifold conv (64->64)
    stats4<<<SB, 256>>>(c1, M, 64, 64);
    stats_final<<<1, 64>>>(M, 64, g3, b3);
    tapconv<27, 64, 64><<<GRID, 256>>>(c1, 64, nbr_coarse, w_sub2, c2, 64, 0, M, M);

    // BN4 -> deconv (64->32) into g_cat[:, 32:64]
    stats4<<<SB, 256>>>(c2, M, 64, 64);
    stats_final<<<1, 64>>>(M, 64, g4, b4);
    deconv2<<<888, 256, SMU>>>(c2, up_cidx, up_k, w_up, cat, N);

    // BN5 over concat -> final conv (64->32) to d_out
    stats4<<<SB, 256>>>(cat, N, 64, 64);
    stats_final<<<1, 64>>>(N, 64, g5, b5);
    tapconv<27, 64, 32><<<GRID, 256>>>(cat, 64, nbr_fine, w_sub3,
                                       (float*)d_out, 32, 0, N, N);
}

// round 6
// speedup vs baseline: 1.3752x; 1.3752x over previous
#include <cuda_runtime.h>

#define NMAX 200704
#define SB 1024   // stats partial blocks

__device__ float g_part[SB * 128];
__device__ float g_scale[64];
__device__ float g_shift[64];
__device__ float g_cat[(size_t)NMAX * 64];   // [N][64]: skip || upsampled
__device__ float g_c1[(size_t)NMAX * 64];    // [M][64]
__device__ float g_c2[(size_t)NMAX * 64];    // [M][64]

// ---------------------------------------------------------------------------
// Batch stats: float4 lanes, deterministic two-stage reduction.
// ---------------------------------------------------------------------------
__global__ void __launch_bounds__(256)
stats4(const float* __restrict__ x, int n, int C, int ld) {
    __shared__ float4 sm[512];
    const int tid = threadIdx.x;
    const int V = C / 4;
    const int rpi = 256 / V;
    const int c4 = tid % V;
    const int rg = tid / V;
    float4 s = {0.f, 0.f, 0.f, 0.f}, q = {0.f, 0.f, 0.f, 0.f};
    for (int r = blockIdx.x * rpi + rg; r < n; r += gridDim.x * rpi) {
        float4 v = *(const float4*)(x + (size_t)r * ld + 4 * c4);
        s.x += v.x; s.y += v.y; s.z += v.z; s.w += v.w;
        q.x += v.x * v.x; q.y += v.y * v.y; q.z += v.z * v.z; q.w += v.w * v.w;
    }
    sm[tid] = s;
    sm[256 + tid] = q;
    __syncthreads();
    if (rg == 0) {
        float4 ts = {0.f, 0.f, 0.f, 0.f}, tq = {0.f, 0.f, 0.f, 0.f};
        for (int j = 0; j < rpi; j++) {
            float4 a = sm[j * V + c4];
            ts.x += a.x; ts.y += a.y; ts.z += a.z; ts.w += a.w;
            float4 b = sm[256 + j * V + c4];
            tq.x += b.x; tq.y += b.y; tq.z += b.z; tq.w += b.w;
        }
        float* p = g_part + blockIdx.x * 128 + 4 * c4;
        p[0] = ts.x; p[1] = ts.y; p[2] = ts.z; p[3] = ts.w;
        p[64] = tq.x; p[65] = tq.y; p[66] = tq.z; p[67] = tq.w;
    }
}

__global__ void stats_final(int n, int C, const float* __restrict__ gg, const float* __restrict__ bb) {
    int c = threadIdx.x;
    if (c >= C) return;
    float s0 = 0.f, s1 = 0.f, s2 = 0.f, s3 = 0.f;
    float q0 = 0.f, q1 = 0.f, q2 = 0.f, q3 = 0.f;
    for (int b = 0; b < SB; b += 4) {
        s0 += g_part[(b + 0) * 128 + c];      q0 += g_part[(b + 0) * 128 + 64 + c];
        s1 += g_part[(b + 1) * 128 + c];      q1 += g_part[(b + 1) * 128 + 64 + c];
        s2 += g_part[(b + 2) * 128 + c];      q2 += g_part[(b + 2) * 128 + 64 + c];
        s3 += g_part[(b + 3) * 128 + c];      q3 += g_part[(b + 3) * 128 + 64 + c];
    }
    float s = (s0 + s1) + (s2 + s3);
    float q = (q0 + q1) + (q2 + q3);
    float inv_n = 1.f / (float)n;
    float mu = s * inv_n;
    float var = q * inv_n - mu * mu;
    float sc = gg[c] * rsqrtf(var + 1e-4f);
    g_scale[c] = sc;
    g_shift[c] = bb[c] - mu * sc;
}

// ---------------------------------------------------------------------------
// Tap-major, weight-stationary sparse conv (shfl x-broadcast).
// Virtual taps: vk = (k, ci-half). Each warp holds exactly wreg[32]
// (one ci-half x one 32-wide co slice) -> no spill at 85-reg cap.
// Partial results combine via deterministic ordered RMW: a fixed warp owns
// each row stripe and processes all vk sequentially in fixed order.
// Prefetch: next stripe's idx vector + next valid pair's gather row.
// ---------------------------------------------------------------------------
template <int K, int Cin, int Cout>
__global__ void __launch_bounds__(256, 3)
tapconv(const float* __restrict__ in, int ldin,
        const int* __restrict__ nbr,          // [K][M]
        const float* __restrict__ W,          // [K][Cin][Cout]
        float* __restrict__ out, int ldout, int outOff,
        int M, int P) {
    const int tid = threadIdx.x;
    const int lane = tid & 31;
    const int w = tid >> 5;
    constexpr int HW = Cout / 32;       // warps per row stripe (co split)
    constexpr int NWP = 8 / HW;         // row stripes per block
    constexpr int CIH = Cin / 32;       // ci halves
    const int wp = w / HW;
    const int half = w % HW;
    const int coB = half * 32;

    const int range = (M + gridDim.x - 1) / gridDim.x;
    const int b0 = blockIdx.x * range;
    const int b1 = min(M, b0 + range);

    for (int i = tid; i < (b1 - b0) * Cout; i += 256) {
        int r = b0 + i / Cout, c = i % Cout;
        out[(size_t)r * ldout + outOff + c] = 0.f;
    }
    __syncthreads();
    if (b0 >= b1) return;

    for (int vk = 0; vk < K * CIH; vk++) {
        const int k = (CIH == 1) ? vk : (vk >> 1);
        const int h = (CIH == 1) ? 0 : (vk & 1);
        const int ciB = h * 32;
        const float sc = g_scale[ciB + lane];
        const float sh = g_shift[ciB + lane];

        float wreg[32];
        const float* Wk = W + (size_t)k * Cin * Cout + (size_t)ciB * Cout;
#pragma unroll
        for (int ci = 0; ci < 32; ci++) wreg[ci] = Wk[ci * Cout + coB + lane];
        const int* nk = nbr + (size_t)k * M;

        int rb = b0 + wp * 32;
        if (rb >= b1) continue;
        int idxl = (rb + lane < b1) ? nk[rb + lane] : P;
        while (rb < b1) {
            const int rbn = rb + NWP * 32;
            int idxln = (rbn + lane < b1) ? nk[rbn + lane] : P;  // next-stripe prefetch
            unsigned mask = __ballot_sync(0xffffffffu, idxl < P);
            if (mask) {
                int t = __ffs(mask) - 1;
                int idx = __shfl_sync(0xffffffffu, idxl, t);
                float v = in[(size_t)idx * ldin + ciB + lane];
                while (true) {
                    mask &= mask - 1;
                    int tn = 0; float pv = 0.f;
                    if (mask) {                       // next-pair prefetch
                        tn = __ffs(mask) - 1;
                        int idxn = __shfl_sync(0xffffffffu, idxl, tn);
                        pv = in[(size_t)idxn * ldin + ciB + lane];
                    }
                    float x = fmaxf(fmaf(v, sc, sh), 0.f);
                    float a0 = 0.f, a1 = 0.f, a2 = 0.f, a3 = 0.f;
#pragma unroll
                    for (int i = 0; i < 8; i++) {
                        float xa = __shfl_sync(0xffffffffu, x, 4 * i + 0);
                        float xb = __shfl_sync(0xffffffffu, x, 4 * i + 1);
                        float xc = __shfl_sync(0xffffffffu, x, 4 * i + 2);
                        float xd = __shfl_sync(0xffffffffu, x, 4 * i + 3);
                        a0 = fmaf(xa, wreg[4 * i + 0], a0);
                        a1 = fmaf(xb, wreg[4 * i + 1], a1);
                        a2 = fmaf(xc, wreg[4 * i + 2], a2);
                        a3 = fmaf(xd, wreg[4 * i + 3], a3);
                    }
                    float* po = out + (size_t)(rb + t) * ldout + outOff + coB + lane;
                    *po += (a0 + a1) + (a2 + a3);
                    if (!mask) break;
                    t = tn; v = pv;
                }
            }
            rb = rbn; idxl = idxln;
        }
    }
}

// ---------------------------------------------------------------------------
// Deconv (upsample, 1 tap per fine voxel): weights in smem, shfl x-broadcast,
// row prefetch, 4-way accumulator ILP.
// ---------------------------------------------------------------------------
__global__ void __launch_bounds__(256, 3)
deconv2(const float* __restrict__ in,          // [M][64]
        const int* __restrict__ up_cidx,       // [N]
        const int* __restrict__ up_k,          // [N]
        const float* __restrict__ W,           // [8][64][32]
        float* __restrict__ out,               // g_cat, cols 32:64
        int n) {
    extern __shared__ float Ws[];              // 8*64*32
    for (int i = threadIdx.x; i < 8 * 2048; i += 256) Ws[i] = W[i];
    __syncthreads();

    const int lane = threadIdx.x & 31;
    const int w = threadIdx.x >> 5;
    const float sc0 = g_scale[lane], sh0 = g_shift[lane];
    const float sc1 = g_scale[lane + 32], sh1 = g_shift[lane + 32];

    const int gw = blockIdx.x * 8 + w;
    const int stride = gridDim.x * 8;
    int r = gw;
    float v0 = 0.f, v1 = 0.f;
    int k = 0;
    if (r < n) {
        int c = up_cidx[r];
        k = up_k[r];
        v0 = in[(size_t)c * 64 + lane];
        v1 = in[(size_t)c * 64 + 32 + lane];
    }
    while (r < n) {
        const int rn = r + stride;
        float p0 = 0.f, p1 = 0.f;
        int kn = 0;
        if (rn < n) {
            int cn = up_cidx[rn];
            kn = up_k[rn];
            p0 = in[(size_t)cn * 64 + lane];
            p1 = in[(size_t)cn * 64 + 32 + lane];
        }
        float x0 = fmaxf(fmaf(v0, sc0, sh0), 0.f);
        float x1 = fmaxf(fmaf(v1, sc1, sh1), 0.f);
        const float* Wt = Ws + k * 2048;
        float a0 = 0.f, a1 = 0.f, a2 = 0.f, a3 = 0.f;
#pragma unroll
        for (int ci = 0; ci < 64; ci += 4) {
            float xa = __shfl_sync(0xffffffffu, (ci + 0 < 32) ? x0 : x1, (ci + 0) & 31);
            float xb = __shfl_sync(0xffffffffu, (ci + 1 < 32) ? x0 : x1, (ci + 1) & 31);
            float xc = __shfl_sync(0xffffffffu, (ci + 2 < 32) ? x0 : x1, (ci + 2) & 31);
            float xd = __shfl_sync(0xffffffffu, (ci + 3 < 32) ? x0 : x1, (ci + 3) & 31);
            a0 = fmaf(xa, Wt[(ci + 0) * 32 + lane], a0);
            a1 = fmaf(xb, Wt[(ci + 1) * 32 + lane], a1);
            a2 = fmaf(xc, Wt[(ci + 2) * 32 + lane], a2);
            a3 = fmaf(xd, Wt[(ci + 3) * 32 + lane], a3);
        }
        out[(size_t)r * 64 + 32 + lane] = (a0 + a1) + (a2 + a3);
        r = rn; v0 = p0; v1 = p1; k = kn;
    }
}

// ---------------------------------------------------------------------------
extern "C" void kernel_launch(void* const* d_in, const int* in_sizes, int n_in,
                              void* d_out, int out_size) {
    (void)n_in; (void)out_size;
    const float* feat    = (const float*)d_in[0];
    const float* w_sub1  = (const float*)d_in[1];
    const float* w_down  = (const float*)d_in[2];
    const float* w_sub2  = (const float*)d_in[3];
    const float* w_up    = (const float*)d_in[4];
    const float* w_sub3  = (const float*)d_in[5];
    const float* g1 = (const float*)d_in[6],  *b1 = (const float*)d_in[7];
    const float* g2 = (const float*)d_in[8],  *b2 = (const float*)d_in[9];
    const float* g3 = (const float*)d_in[10], *b3 = (const float*)d_in[11];
    const float* g4 = (const float*)d_in[12], *b4 = (const float*)d_in[13];
    const float* g5 = (const float*)d_in[14], *b5 = (const float*)d_in[15];
    const int* nbr_fine   = (const int*)d_in[16];
    const int* nbr_coarse = (const int*)d_in[17];
    const int* down_idx   = (const int*)d_in[18];
    const int* up_cidx    = (const int*)d_in[19];
    const int* up_k       = (const int*)d_in[20];

    const int N = in_sizes[0] / 32;
    const int M = in_sizes[17] / 27;

    void* p;
    cudaGetSymbolAddress(&p, g_cat); float* cat = (float*)p;
    cudaGetSymbolAddress(&p, g_c1);  float* c1  = (float*)p;
    cudaGetSymbolAddress(&p, g_c2);  float* c2  = (float*)p;

    const int SMU = 8 * 64 * 32 * 4;   // 64KB dynamic (weights)
    cudaFuncSetAttribute(deconv2, cudaFuncAttributeMaxDynamicSharedMemorySize, SMU);

    const int GRID = 888;   // 256-thread blocks, 3/SM resident, 2 waves

    // BN1 -> sub1 (skip) into g_cat[:, 0:32]
    stats4<<<SB, 256>>>(feat, N, 32, 32);
    stats_final<<<1, 64>>>(N, 32, g1, b1);
    tapconv<27, 32, 32><<<GRID, 256>>>(feat, 32, nbr_fine, w_sub1, cat, 64, 0, N, N);

    // BN2 -> down conv (32->64)
    stats4<<<SB, 256>>>(cat, N, 32, 64);
    stats_final<<<1, 64>>>(N, 32, g2, b2);
    tapconv<8, 32, 64><<<GRID, 256>>>(cat, 64, down_idx, w_down, c1, 64, 0, M, N);

    // BN3 -> coarse submanifold conv (64->64)
    stats4<<<SB, 256>>>(c1, M, 64, 64);
    stats_final<<<1, 64>>>(M, 64, g3, b3);
    tapconv<27, 64, 64><<<GRID, 256>>>(c1, 64, nbr_coarse, w_sub2, c2, 64, 0, M, M);

    // BN4 -> deconv (64->32) into g_cat[:, 32:64]
    stats4<<<SB, 256>>>(c2, M, 64, 64);
    stats_final<<<1, 64>>>(M, 64, g4, b4);
    deconv2<<<888, 256, SMU>>>(c2, up_cidx, up_k, w_up, cat, N);

    // BN5 over concat -> final conv (64->32) to d_out
    stats4<<<SB, 256>>>(cat, N, 64, 64);
    stats_final<<<1, 64>>>(N, 64, g5, b5);
    tapconv<27, 64, 32><<<GRID, 256>>>(cat, 64, nbr_fine, w_sub3,
                                       (float*)d_out, 32, 0, N, N);
}

// round 8
// speedup vs baseline: 1.4154x; 1.0292x over previous
#include <cuda_runtime.h>

#define NMAX 200704
#define SB 1024   // stats partial blocks

__device__ float g_part[SB * 128];
__device__ float g_scale[64];
__device__ float g_shift[64];
__device__ float g_cat[(size_t)NMAX * 64];   // [N][64]: skip || upsampled
__device__ float g_c1[(size_t)NMAX * 64];    // [M][64]
__device__ float g_c2[(size_t)NMAX * 64];    // [M][64]

// ---------------------------------------------------------------------------
// Batch stats: float4 lanes, deterministic two-stage reduction.
// ---------------------------------------------------------------------------
__global__ void __launch_bounds__(256)
stats4(const float* __restrict__ x, int n, int C, int ld) {
    __shared__ float4 sm[512];
    const int tid = threadIdx.x;
    const int V = C / 4;
    const int rpi = 256 / V;
    const int c4 = tid % V;
    const int rg = tid / V;
    float4 s = {0.f, 0.f, 0.f, 0.f}, q = {0.f, 0.f, 0.f, 0.f};
    for (int r = blockIdx.x * rpi + rg; r < n; r += gridDim.x * rpi) {
        float4 v = *(const float4*)(x + (size_t)r * ld + 4 * c4);
        s.x += v.x; s.y += v.y; s.z += v.z; s.w += v.w;
        q.x += v.x * v.x; q.y += v.y * v.y; q.z += v.z * v.z; q.w += v.w * v.w;
    }
    sm[tid] = s;
    sm[256 + tid] = q;
    __syncthreads();
    if (rg == 0) {
        float4 ts = {0.f, 0.f, 0.f, 0.f}, tq = {0.f, 0.f, 0.f, 0.f};
        for (int j = 0; j < rpi; j++) {
            float4 a = sm[j * V + c4];
            ts.x += a.x; ts.y += a.y; ts.z += a.z; ts.w += a.w;
            float4 b = sm[256 + j * V + c4];
            tq.x += b.x; tq.y += b.y; tq.z += b.z; tq.w += b.w;
        }
        float* p = g_part + blockIdx.x * 128 + 4 * c4;
        p[0] = ts.x; p[1] = ts.y; p[2] = ts.z; p[3] = ts.w;
        p[64] = tq.x; p[65] = tq.y; p[66] = tq.z; p[67] = tq.w;
    }
}

__global__ void stats_final(int n, int C, const float* __restrict__ gg, const float* __restrict__ bb) {
    int c = threadIdx.x;
    if (c >= C) return;
    float s0 = 0.f, s1 = 0.f, s2 = 0.f, s3 = 0.f;
    float q0 = 0.f, q1 = 0.f, q2 = 0.f, q3 = 0.f;
    for (int b = 0; b < SB; b += 4) {
        s0 += g_part[(b + 0) * 128 + c];      q0 += g_part[(b + 0) * 128 + 64 + c];
        s1 += g_part[(b + 1) * 128 + c];      q1 += g_part[(b + 1) * 128 + 64 + c];
        s2 += g_part[(b + 2) * 128 + c];      q2 += g_part[(b + 2) * 128 + 64 + c];
        s3 += g_part[(b + 3) * 128 + c];      q3 += g_part[(b + 3) * 128 + 64 + c];
    }
    float s = (s0 + s1) + (s2 + s3);
    float q = (q0 + q1) + (q2 + q3);
    float inv_n = 1.f / (float)n;
    float mu = s * inv_n;
    float var = q * inv_n - mu * mu;
    float sc = gg[c] * rsqrtf(var + 1e-4f);
    g_scale[c] = sc;
    g_shift[c] = bb[c] - mu * sc;
}

// ---------------------------------------------------------------------------
// Tap-major weight-stationary sparse conv, float2-co per lane.
// Virtual taps vk = (k, 16-wide ci slice); wreg = float2[16] (32 regs).
// Cout=64: lane owns co {2*lane, 2*lane+1}; one row per visit; 16 shfl / 32 fma.
// Cout=32: lane owns co {2*(lane&15), +1}; TWO rows per visit (half-warps),
//          x broadcast via SHFL.IDX src = (lane&16)|ci.
// Deterministic ordered RMW: warp owns its row stripes across all vk.
// ---------------------------------------------------------------------------
template <int K, int Cin, int Cout>
__global__ void __launch_bounds__(256, 3)
tapconv(const float* __restrict__ in, int ldin,
        const int* __restrict__ nbr,          // [K][M]
        const float* __restrict__ W,          // [K][Cin][Cout]
        float* __restrict__ out, int ldout, int outOff,
        int M, int P) {
    const int tid = threadIdx.x;
    const int lane = tid & 31;
    const int w = tid >> 5;
    constexpr int VIS = Cin / 16;             // ci slices per tap
    const int l15 = lane & 15;
    const bool hi = lane >= 16;

    const int range = (M + gridDim.x - 1) / gridDim.x;
    const int b0 = blockIdx.x * range;
    const int b1 = min(M, b0 + range);

    for (int i = tid; i < (b1 - b0) * Cout; i += 256) {
        int r = b0 + i / Cout, c = i % Cout;
        out[(size_t)r * ldout + outOff + c] = 0.f;
    }
    __syncthreads();
    if (b0 >= b1) return;

    for (int vk = 0; vk < K * VIS; vk++) {
        const int k = vk / VIS;
        const int ciB = (vk % VIS) * 16;
        const float sc = g_scale[ciB + l15];
        const float sh = g_shift[ciB + l15];

        float2 wreg[16];
        const int co2 = (Cout == 64) ? (2 * lane) : (2 * l15);
        const float* Wk = W + (size_t)k * Cin * Cout + (size_t)ciB * Cout;
#pragma unroll
        for (int ci = 0; ci < 16; ci++)
            wreg[ci] = *(const float2*)(Wk + ci * Cout + co2);
        const int* nk = nbr + (size_t)k * M;

        int rb = b0 + w * 32;
        if (rb >= b1) continue;
        int idxl = (rb + lane < b1) ? nk[rb + lane] : P;
        while (rb < b1) {
            const int rbn = rb + 8 * 32;
            int idxln = (rbn + lane < b1) ? nk[rbn + lane] : P;   // next-stripe prefetch
            unsigned mask = __ballot_sync(0xffffffffu, idxl < P);

            if (Cout == 64) {
                if (mask) {
                    int t = __ffs(mask) - 1;
                    int idx = __shfl_sync(0xffffffffu, idxl, t);
                    float v = in[(size_t)idx * ldin + ciB + l15];
                    while (true) {
                        mask &= mask - 1;
                        int tn = 0; float pv = 0.f;
                        if (mask) {                    // next-pair prefetch
                            tn = __ffs(mask) - 1;
                            int idxn = __shfl_sync(0xffffffffu, idxl, tn);
                            pv = in[(size_t)idxn * ldin + ciB + l15];
                        }
                        float x = fmaxf(fmaf(v, sc, sh), 0.f);
                        float2 aA = {0.f, 0.f}, aB = {0.f, 0.f};
#pragma unroll
                        for (int ci = 0; ci < 16; ci += 2) {
                            float xe = __shfl_sync(0xffffffffu, x, ci);
                            float xo = __shfl_sync(0xffffffffu, x, ci + 1);
                            aA.x = fmaf(xe, wreg[ci].x, aA.x);
                            aA.y = fmaf(xe, wreg[ci].y, aA.y);
                            aB.x = fmaf(xo, wreg[ci + 1].x, aB.x);
                            aB.y = fmaf(xo, wreg[ci + 1].y, aB.y);
                        }
                        float2* po = (float2*)(out + (size_t)(rb + t) * ldout + outOff) + lane;
                        float2 cur = *po;
                        cur.x += aA.x + aB.x; cur.y += aA.y + aB.y;
                        *po = cur;
                        if (!mask) break;
                        t = tn; v = pv;
                    }
                }
            } else {   // Cout == 32: two rows per visit
                if (mask) {
                    int t0 = __ffs(mask) - 1;
                    unsigned m2 = mask & (mask - 1);
                    int t1 = m2 ? (__ffs(m2) - 1) : t0;
                    bool v2 = (m2 != 0);
                    m2 = v2 ? (m2 & (m2 - 1)) : 0u;
                    int idx = __shfl_sync(0xffffffffu, idxl, hi ? t1 : t0);
                    float v = in[(size_t)idx * ldin + ciB + l15];
                    while (true) {
                        int nt0 = 0, nt1 = 0; bool nv2 = false;
                        const bool hasN = (m2 != 0);
                        float pv = 0.f;
                        if (hasN) {                    // next-two prefetch
                            nt0 = __ffs(m2) - 1;
                            unsigned mm = m2 & (m2 - 1);
                            nt1 = mm ? (__ffs(mm) - 1) : nt0;
                            nv2 = (mm != 0);
                            m2 = nv2 ? (mm & (mm - 1)) : 0u;
                            int nidx = __shfl_sync(0xffffffffu, idxl, hi ? nt1 : nt0);
                            pv = in[(size_t)nidx * ldin + ciB + l15];
                        }
                        float x = fmaxf(fmaf(v, sc, sh), 0.f);
                        float2 aA = {0.f, 0.f}, aB = {0.f, 0.f};
                        const int srcB = lane & 16;
#pragma unroll
                        for (int ci = 0; ci < 16; ci += 2) {
                            float xe = __shfl_sync(0xffffffffu, x, srcB | ci);
                            float xo = __shfl_sync(0xffffffffu, x, srcB | (ci + 1));
                            aA.x = fmaf(xe, wreg[ci].x, aA.x);
                            aA.y = fmaf(xe, wreg[ci].y, aA.y);
                            aB.x = fmaf(xo, wreg[ci + 1].x, aB.x);
                            aB.y = fmaf(xo, wreg[ci + 1].y, aB.y);
                        }
                        if (!hi || v2) {
                            int r = rb + (hi ? t1 : t0);
                            float2* po = (float2*)(out + (size_t)r * ldout + outOff) + l15;
                            float2 cur = *po;
                            cur.x += aA.x + aB.x; cur.y += aA.y + aB.y;
                            *po = cur;
                        }
                        if (!hasN) break;
                        t0 = nt0; t1 = nt1; v2 = nv2; v = pv;
                    }
                }
            }
            rb = rbn; idxl = idxln;
        }
    }
}

// ---------------------------------------------------------------------------
// Deconv (upsample, 1 tap per fine voxel): weights in smem, shfl x-broadcast,
// row prefetch, 4-way accumulator ILP.
// ---------------------------------------------------------------------------
__global__ void __launch_bounds__(256, 3)
deconv2(const float* __restrict__ in,          // [M][64]
        const int* __restrict__ up_cidx,       // [N]
        const int* __restrict__ up_k,          // [N]
        const float* __restrict__ W,           // [8][64][32]
        float* __restrict__ out,               // g_cat, cols 32:64
        int n) {
    extern __shared__ float Ws[];              // 8*64*32
    for (int i = threadIdx.x; i < 8 * 2048; i += 256) Ws[i] = W[i];
    __syncthreads();

    const int lane = threadIdx.x & 31;
    const int w = threadIdx.x >> 5;
    const float sc0 = g_scale[lane], sh0 = g_shift[lane];
    const float sc1 = g_scale[lane + 32], sh1 = g_shift[lane + 32];

    const int gw = blockIdx.x * 8 + w;
    const int stride = gridDim.x * 8;
    int r = gw;
    float v0 = 0.f, v1 = 0.f;
    int k = 0;
    if (r < n) {
        int c = up_cidx[r];
        k = up_k[r];
        v0 = in[(size_t)c * 64 + lane];
        v1 = in[(size_t)c * 64 + 32 + lane];
    }
    while (r < n) {
        const int rn = r + stride;
        float p0 = 0.f, p1 = 0.f;
        int kn = 0;
        if (rn < n) {
            int cn = up_cidx[rn];
            kn = up_k[rn];
            p0 = in[(size_t)cn * 64 + lane];
            p1 = in[(size_t)cn * 64 + 32 + lane];
        }
        float x0 = fmaxf(fmaf(v0, sc0, sh0), 0.f);
        float x1 = fmaxf(fmaf(v1, sc1, sh1), 0.f);
        const float* Wt = Ws + k * 2048;
        float a0 = 0.f, a1 = 0.f, a2 = 0.f, a3 = 0.f;
#pragma unroll
        for (int ci = 0; ci < 64; ci += 4) {
            float xa = __shfl_sync(0xffffffffu, (ci + 0 < 32) ? x0 : x1, (ci + 0) & 31);
            float xb = __shfl_sync(0xffffffffu, (ci + 1 < 32) ? x0 : x1, (ci + 1) & 31);
            float xc = __shfl_sync(0xffffffffu, (ci + 2 < 32) ? x0 : x1, (ci + 2) & 31);
            float xd = __shfl_sync(0xffffffffu, (ci + 3 < 32) ? x0 : x1, (ci + 3) & 31);
            a0 = fmaf(xa, Wt[(ci + 0) * 32 + lane], a0);
            a1 = fmaf(xb, Wt[(ci + 1) * 32 + lane], a1);
            a2 = fmaf(xc, Wt[(ci + 2) * 32 + lane], a2);
            a3 = fmaf(xd, Wt[(ci + 3) * 32 + lane], a3);
        }
        out[(size_t)r * 64 + 32 + lane] = (a0 + a1) + (a2 + a3);
        r = rn; v0 = p0; v1 = p1; k = kn;
    }
}

// ---------------------------------------------------------------------------
extern "C" void kernel_launch(void* const* d_in, const int* in_sizes, int n_in,
                              void* d_out, int out_size) {
    (void)n_in; (void)out_size;
    const float* feat    = (const float*)d_in[0];
    const float* w_sub1  = (const float*)d_in[1];
    const float* w_down  = (const float*)d_in[2];
    const float* w_sub2  = (const float*)d_in[3];
    const float* w_up    = (const float*)d_in[4];
    const float* w_sub3  = (const float*)d_in[5];
    const float* g1 = (const float*)d_in[6],  *b1 = (const float*)d_in[7];
    const float* g2 = (const float*)d_in[8],  *b2 = (const float*)d_in[9];
    const float* g3 = (const float*)d_in[10], *b3 = (const float*)d_in[11];
    const float* g4 = (const float*)d_in[12], *b4 = (const float*)d_in[13];
    const float* g5 = (const float*)d_in[14], *b5 = (const float*)d_in[15];
    const int* nbr_fine   = (const int*)d_in[16];
    const int* nbr_coarse = (const int*)d_in[17];
    const int* down_idx   = (const int*)d_in[18];
    const int* up_cidx    = (const int*)d_in[19];
    const int* up_k       = (const int*)d_in[20];

    const int N = in_sizes[0] / 32;
    const int M = in_sizes[17] / 27;

    void* p;
    cudaGetSymbolAddress(&p, g_cat); float* cat = (float*)p;
    cudaGetSymbolAddress(&p, g_c1);  float* c1  = (float*)p;
    cudaGetSymbolAddress(&p, g_c2);  float* c2  = (float*)p;

    const int SMU = 8 * 64 * 32 * 4;   // 64KB dynamic (weights)
    cudaFuncSetAttribute(deconv2, cudaFuncAttributeMaxDynamicSharedMemorySize, SMU);

    const int GRID = 888;   // 256-thread blocks, 3/SM resident

    // BN1 -> sub1 (skip) into g_cat[:, 0:32]
    stats4<<<SB, 256>>>(feat, N, 32, 32);
    stats_final<<<1, 64>>>(N, 32, g1, b1);
    tapconv<27, 32, 32><<<GRID, 256>>>(feat, 32, nbr_fine, w_sub1, cat, 64, 0, N, N);

    // BN2 -> down conv (32->64)
    stats4<<<SB, 256>>>(cat, N, 32, 64);
    stats_final<<<1, 64>>>(N, 32, g2, b2);
    tapconv<8, 32, 64><<<GRID, 256>>>(cat, 64, down_idx, w_down, c1, 64, 0, M, N);

    // BN3 -> coarse submanifold conv (64->64)
    stats4<<<SB, 256>>>(c1, M, 64, 64);
    stats_final<<<1, 64>>>(M, 64, g3, b3);
    tapconv<27, 64, 64><<<GRID, 256>>>(c1, 64, nbr_coarse, w_sub2, c2, 64, 0, M, M);

    // BN4 -> deconv (64->32) into g_cat[:, 32:64]
    stats4<<<SB, 256>>>(c2, M, 64, 64);
    stats_final<<<1, 64>>>(M, 64, g4, b4);
    deconv2<<<888, 256, SMU>>>(c2, up_cidx, up_k, w_up, cat, N);

    // BN5 over concat -> final conv (64->32) to d_out
    stats4<<<SB, 256>>>(cat, N, 64, 64);
    stats_final<<<1, 64>>>(N, 64, g5, b5);
    tapconv<27, 64, 32><<<GRID, 256>>>(cat, 64, nbr_fine, w_sub3,
                                       (float*)d_out, 32, 0, N, N);
}

// round 9
// speedup vs baseline: 1.4733x; 1.0409x over previous
#include <cuda_runtime.h>

#define NMAX 200704
#define SB 1024   // stats partial blocks

__device__ float g_part[SB * 128];
__device__ float g_scale[64];
__device__ float g_shift[64];
__device__ float g_cat[(size_t)NMAX * 64];   // [N][64]: skip || upsampled
__device__ float g_c1[(size_t)NMAX * 64];    // [M][64]
__device__ float g_c2[(size_t)NMAX * 64];    // [M][64]

// Dummy kernel: shifts launch order so ncu's fixed capture slot lands on the
// first real conv kernel (sub1) instead of stats4. Deterministic, harmless
// (g_part is fully overwritten by stats4 before any read).
__global__ void probe_pad() { if (threadIdx.x == 0) g_part[0] = 0.f; }

// ---------------------------------------------------------------------------
// Batch stats: float4 lanes, deterministic two-stage reduction.
// ---------------------------------------------------------------------------
__global__ void __launch_bounds__(256)
stats4(const float* __restrict__ x, int n, int C, int ld) {
    __shared__ float4 sm[512];
    const int tid = threadIdx.x;
    const int V = C / 4;
    const int rpi = 256 / V;
    const int c4 = tid % V;
    const int rg = tid / V;
    float4 s = {0.f, 0.f, 0.f, 0.f}, q = {0.f, 0.f, 0.f, 0.f};
    for (int r = blockIdx.x * rpi + rg; r < n; r += gridDim.x * rpi) {
        float4 v = *(const float4*)(x + (size_t)r * ld + 4 * c4);
        s.x += v.x; s.y += v.y; s.z += v.z; s.w += v.w;
        q.x += v.x * v.x; q.y += v.y * v.y; q.z += v.z * v.z; q.w += v.w * v.w;
    }
    sm[tid] = s;
    sm[256 + tid] = q;
    __syncthreads();
    if (rg == 0) {
        float4 ts = {0.f, 0.f, 0.f, 0.f}, tq = {0.f, 0.f, 0.f, 0.f};
        for (int j = 0; j < rpi; j++) {
            float4 a = sm[j * V + c4];
            ts.x += a.x; ts.y += a.y; ts.z += a.z; ts.w += a.w;
            float4 b = sm[256 + j * V + c4];
            tq.x += b.x; tq.y += b.y; tq.z += b.z; tq.w += b.w;
        }
        float* p = g_part + blockIdx.x * 128 + 4 * c4;
        p[0] = ts.x; p[1] = ts.y; p[2] = ts.z; p[3] = ts.w;
        p[64] = tq.x; p[65] = tq.y; p[66] = tq.z; p[67] = tq.w;
    }
}

__global__ void stats_final(int n, int C, const float* __restrict__ gg, const float* __restrict__ bb) {
    int c = threadIdx.x;
    if (c >= C) return;
    float s0 = 0.f, s1 = 0.f, s2 = 0.f, s3 = 0.f;
    float q0 = 0.f, q1 = 0.f, q2 = 0.f, q3 = 0.f;
    for (int b = 0; b < SB; b += 4) {
        s0 += g_part[(b + 0) * 128 + c];      q0 += g_part[(b + 0) * 128 + 64 + c];
        s1 += g_part[(b + 1) * 128 + c];      q1 += g_part[(b + 1) * 128 + 64 + c];
        s2 += g_part[(b + 2) * 128 + c];      q2 += g_part[(b + 2) * 128 + 64 + c];
        s3 += g_part[(b + 3) * 128 + c];      q3 += g_part[(b + 3) * 128 + 64 + c];
    }
    float s = (s0 + s1) + (s2 + s3);
    float q = (q0 + q1) + (q2 + q3);
    float inv_n = 1.f / (float)n;
    float mu = s * inv_n;
    float var = q * inv_n - mu * mu;
    float sc = gg[c] * rsqrtf(var + 1e-4f);
    g_scale[c] = sc;
    g_shift[c] = bb[c] - mu * sc;
}

// ---------------------------------------------------------------------------
// Tap-major weight-stationary sparse conv, float2-co per lane.
// Virtual taps vk = (k, 16-wide ci slice); wreg = float2[16] (32 regs).
// Cout=64: lane owns co {2*lane,2*lane+1}; cross-stripe pipelining: next
//          stripe's idx + ballot + FIRST GATHER issue before current pairs.
// Cout=32: lane owns co {2*(lane&15),+1}; two rows per visit via half-warps.
// Deterministic ordered RMW: warp owns its row stripes across all vk.
// ---------------------------------------------------------------------------
template <int K, int Cin, int Cout>
__global__ void __launch_bounds__(256, 3)
tapconv(const float* __restrict__ in, int ldin,
        const int* __restrict__ nbr,          // [K][M]
        const float* __restrict__ W,          // [K][Cin][Cout]
        float* __restrict__ out, int ldout, int outOff,
        int M, int P) {
    const int tid = threadIdx.x;
    const int lane = tid & 31;
    const int w = tid >> 5;
    constexpr int VIS = Cin / 16;             // ci slices per tap
    const int l15 = lane & 15;
    const bool hi = lane >= 16;

    const int range = (M + gridDim.x - 1) / gridDim.x;
    const int b0 = blockIdx.x * range;
    const int b1 = min(M, b0 + range);

    for (int i = tid; i < (b1 - b0) * Cout; i += 256) {
        int r = b0 + i / Cout, c = i % Cout;
        out[(size_t)r * ldout + outOff + c] = 0.f;
    }
    __syncthreads();
    if (b0 >= b1) return;

    for (int vk = 0; vk < K * VIS; vk++) {
        const int k = vk / VIS;
        const int ciB = (vk % VIS) * 16;
        const float sc = g_scale[ciB + l15];
        const float sh = g_shift[ciB + l15];

        float2 wreg[16];
        const int co2 = (Cout == 64) ? (2 * lane) : (2 * l15);
        const float* Wk = W + (size_t)k * Cin * Cout + (size_t)ciB * Cout;
#pragma unroll
        for (int ci = 0; ci < 16; ci++)
            wreg[ci] = *(const float2*)(Wk + ci * Cout + co2);
        const int* nk = nbr + (size_t)k * M;

        if (Cout == 64) {
            // ---- pipelined across stripes ----
            int rb = b0 + w * 32;
            if (rb >= b1) continue;
            int idxl = (rb + lane < b1) ? nk[rb + lane] : P;
            unsigned mask = __ballot_sync(0xffffffffu, idxl < P);
            int t = 0; float v = 0.f;
            if (mask) {
                t = __ffs(mask) - 1;
                int idx = __shfl_sync(0xffffffffu, idxl, t);
                v = in[(size_t)idx * ldin + ciB + l15];
            }
            while (rb < b1) {
                const int rbn = rb + 8 * 32;
                // next stripe: idx + ballot + head gather, issued BEFORE pairs
                int idxln = (rbn + lane < b1) ? nk[rbn + lane] : P;
                unsigned maskn = __ballot_sync(0xffffffffu, idxln < P);
                int th = 0; float vh = 0.f;
                if (maskn) {
                    th = __ffs(maskn) - 1;
                    int idxh = __shfl_sync(0xffffffffu, idxln, th);
                    vh = in[(size_t)idxh * ldin + ciB + l15];
                }
                while (mask) {
                    mask &= mask - 1;
                    int tn = 0; float pv = 0.f;
                    if (mask) {                    // next-pair prefetch
                        tn = __ffs(mask) - 1;
                        int idxn = __shfl_sync(0xffffffffu, idxl, tn);
                        pv = in[(size_t)idxn * ldin + ciB + l15];
                    }
                    float x = fmaxf(fmaf(v, sc, sh), 0.f);
                    float2 aA = {0.f, 0.f}, aB = {0.f, 0.f};
#pragma unroll
                    for (int ci = 0; ci < 16; ci += 2) {
                        float xe = __shfl_sync(0xffffffffu, x, ci);
                        float xo = __shfl_sync(0xffffffffu, x, ci + 1);
                        aA.x = fmaf(xe, wreg[ci].x, aA.x);
                        aA.y = fmaf(xe, wreg[ci].y, aA.y);
                        aB.x = fmaf(xo, wreg[ci + 1].x, aB.x);
                        aB.y = fmaf(xo, wreg[ci + 1].y, aB.y);
                    }
                    float2* po = (float2*)(out + (size_t)(rb + t) * ldout + outOff) + lane;
                    float2 cur = *po;
                    cur.x += aA.x + aB.x; cur.y += aA.y + aB.y;
                    *po = cur;
                    t = tn; v = pv;
                }
                rb = rbn; idxl = idxln; mask = maskn; t = th; v = vh;
            }
        } else {
            // ---- Cout == 32: two rows per visit ----
            int rb = b0 + w * 32;
            if (rb >= b1) continue;
            int idxl = (rb + lane < b1) ? nk[rb + lane] : P;
            while (rb < b1) {
                const int rbn = rb + 8 * 32;
                int idxln = (rbn + lane < b1) ? nk[rbn + lane] : P;   // next-stripe prefetch
                unsigned mask = __ballot_sync(0xffffffffu, idxl < P);
                if (mask) {
                    int t0 = __ffs(mask) - 1;
                    unsigned m2 = mask & (mask - 1);
                    int t1 = m2 ? (__ffs(m2) - 1) : t0;
                    bool v2 = (m2 != 0);
                    m2 = v2 ? (m2 & (m2 - 1)) : 0u;
                    int idx = __shfl_sync(0xffffffffu, idxl, hi ? t1 : t0);
                    float v = in[(size_t)idx * ldin + ciB + l15];
                    while (true) {
                        int nt0 = 0, nt1 = 0; bool nv2 = false;
                        const bool hasN = (m2 != 0);
                        float pv = 0.f;
                        if (hasN) {                    // next-two prefetch
                            nt0 = __ffs(m2) - 1;
                            unsigned mm = m2 & (m2 - 1);
                            nt1 = mm ? (__ffs(mm) - 1) : nt0;
                            nv2 = (mm != 0);
                            m2 = nv2 ? (mm & (mm - 1)) : 0u;
                            int nidx = __shfl_sync(0xffffffffu, idxl, hi ? nt1 : nt0);
                            pv = in[(size_t)nidx * ldin + ciB + l15];
                        }
                        float x = fmaxf(fmaf(v, sc, sh), 0.f);
                        float2 aA = {0.f, 0.f}, aB = {0.f, 0.f};
                        const int srcB = lane & 16;
#pragma unroll
                        for (int ci = 0; ci < 16; ci += 2) {
                            float xe = __shfl_sync(0xffffffffu, x, srcB | ci);
                            float xo = __shfl_sync(0xffffffffu, x, srcB | (ci + 1));
                            aA.x = fmaf(xe, wreg[ci].x, aA.x);
                            aA.y = fmaf(xe, wreg[ci].y, aA.y);
                            aB.x = fmaf(xo, wreg[ci + 1].x, aB.x);
                            aB.y = fmaf(xo, wreg[ci + 1].y, aB.y);
                        }
                        if (!hi || v2) {
                            int r = rb + (hi ? t1 : t0);
                            float2* po = (float2*)(out + (size_t)r * ldout + outOff) + l15;
                            float2 cur = *po;
                            cur.x += aA.x + aB.x; cur.y += aA.y + aB.y;
                            *po = cur;
                        }
                        if (!hasN) break;
                        t0 = nt0; t1 = nt1; v2 = nv2; v = pv;
                    }
                }
                rb = rbn; idxl = idxln;
            }
        }
    }
}

// ---------------------------------------------------------------------------
// Deconv (upsample, 1 tap per fine voxel): weights in smem, shfl x-broadcast,
// row prefetch, 4-way accumulator ILP.
// ---------------------------------------------------------------------------
__global__ void __launch_bounds__(256, 3)
deconv2(const float* __restrict__ in,          // [M][64]
        const int* __restrict__ up_cidx,       // [N]
        const int* __restrict__ up_k,          // [N]
        const float* __restrict__ W,           // [8][64][32]
        float* __restrict__ out,               // g_cat, cols 32:64
        int n) {
    extern __shared__ float Ws[];              // 8*64*32
    for (int i = threadIdx.x; i < 8 * 2048; i += 256) Ws[i] = W[i];
    __syncthreads();

    const int lane = threadIdx.x & 31;
    const int w = threadIdx.x >> 5;
    const float sc0 = g_scale[lane], sh0 = g_shift[lane];
    const float sc1 = g_scale[lane + 32], sh1 = g_shift[lane + 32];

    const int gw = blockIdx.x * 8 + w;
    const int stride = gridDim.x * 8;
    int r = gw;
    float v0 = 0.f, v1 = 0.f;
    int k = 0;
    if (r < n) {
        int c = up_cidx[r];
        k = up_k[r];
        v0 = in[(size_t)c * 64 + lane];
        v1 = in[(size_t)c * 64 + 32 + lane];
    }
    while (r < n) {
        const int rn = r + stride;
        float p0 = 0.f, p1 = 0.f;
        int kn = 0;
        if (rn < n) {
            int cn = up_cidx[rn];
            kn = up_k[rn];
            p0 = in[(size_t)cn * 64 + lane];
            p1 = in[(size_t)cn * 64 + 32 + lane];
        }
        float x0 = fmaxf(fmaf(v0, sc0, sh0), 0.f);
        float x1 = fmaxf(fmaf(v1, sc1, sh1), 0.f);
        const float* Wt = Ws + k * 2048;
        float a0 = 0.f, a1 = 0.f, a2 = 0.f, a3 = 0.f;
#pragma unroll
        for (int ci = 0; ci < 64; ci += 4) {
            float xa = __shfl_sync(0xffffffffu, (ci + 0 < 32) ? x0 : x1, (ci + 0) & 31);
            float xb = __shfl_sync(0xffffffffu, (ci + 1 < 32) ? x0 : x1, (ci + 1) & 31);
            float xc = __shfl_sync(0xffffffffu, (ci + 2 < 32) ? x0 : x1, (ci + 2) & 31);
            float xd = __shfl_sync(0xffffffffu, (ci + 3 < 32) ? x0 : x1, (ci + 3) & 31);
            a0 = fmaf(xa, Wt[(ci + 0) * 32 + lane], a0);
            a1 = fmaf(xb, Wt[(ci + 1) * 32 + lane], a1);
            a2 = fmaf(xc, Wt[(ci + 2) * 32 + lane], a2);
            a3 = fmaf(xd, Wt[(ci + 3) * 32 + lane], a3);
        }
        out[(size_t)r * 64 + 32 + lane] = (a0 + a1) + (a2 + a3);
        r = rn; v0 = p0; v1 = p1; k = kn;
    }
}

// ---------------------------------------------------------------------------
extern "C" void kernel_launch(void* const* d_in, const int* in_sizes, int n_in,
                              void* d_out, int out_size) {
    (void)n_in; (void)out_size;
    const float* feat    = (const float*)d_in[0];
    const float* w_sub1  = (const float*)d_in[1];
    const float* w_down  = (const float*)d_in[2];
    const float* w_sub2  = (const float*)d_in[3];
    const float* w_up    = (const float*)d_in[4];
    const float* w_sub3  = (const float*)d_in[5];
    const float* g1 = (const float*)d_in[6],  *b1 = (const float*)d_in[7];
    const float* g2 = (const float*)d_in[8],  *b2 = (const float*)d_in[9];
    const float* g3 = (const float*)d_in[10], *b3 = (const float*)d_in[11];
    const float* g4 = (const float*)d_in[12], *b4 = (const float*)d_in[13];
    const float* g5 = (const float*)d_in[14], *b5 = (const float*)d_in[15];
    const int* nbr_fine   = (const int*)d_in[16];
    const int* nbr_coarse = (const int*)d_in[17];
    const int* down_idx   = (const int*)d_in[18];
    const int* up_cidx    = (const int*)d_in[19];
    const int* up_k       = (const int*)d_in[20];

    const int N = in_sizes[0] / 32;
    const int M = in_sizes[17] / 27;

    void* p;
    cudaGetSymbolAddress(&p, g_cat); float* cat = (float*)p;
    cudaGetSymbolAddress(&p, g_c1);  float* c1  = (float*)p;
    cudaGetSymbolAddress(&p, g_c2);  float* c2  = (float*)p;

    const int SMU = 8 * 64 * 32 * 4;   // 64KB dynamic (weights)
    cudaFuncSetAttribute(deconv2, cudaFuncAttributeMaxDynamicSharedMemorySize, SMU);

    const int GRID = 444;   // 148 SMs x 3 blocks/SM: exactly one wave

    // shift launch order so ncu's fixed capture slot lands on sub1 conv
    probe_pad<<<1, 32>>>();

    // BN1 -> sub1 (skip) into g_cat[:, 0:32]
    stats4<<<SB, 256>>>(feat, N, 32, 32);
    stats_final<<<1, 64>>>(N, 32, g1, b1);
    tapconv<27, 32, 32><<<GRID, 256>>>(feat, 32, nbr_fine, w_sub1, cat, 64, 0, N, N);

    // BN2 -> down conv (32->64)
    stats4<<<SB, 256>>>(cat, N, 32, 64);
    stats_final<<<1, 64>>>(N, 32, g2, b2);
    tapconv<8, 32, 64><<<GRID, 256>>>(cat, 64, down_idx, w_down, c1, 64, 0, M, N);

    // BN3 -> coarse submanifold conv (64->64)
    stats4<<<SB, 256>>>(c1, M, 64, 64);
    stats_final<<<1, 64>>>(M, 64, g3, b3);
    tapconv<27, 64, 64><<<GRID, 256>>>(c1, 64, nbr_coarse, w_sub2, c2, 64, 0, M, M);

    // BN4 -> deconv (64->32) into g_cat[:, 32:64]
    stats4<<<SB, 256>>>(c2, M, 64, 64);
    stats_final<<<1, 64>>>(M, 64, g4, b4);
    deconv2<<<888, 256, SMU>>>(c2, up_cidx, up_k, w_up, cat, N);

    // BN5 over concat -> final conv (64->32) to d_out
    stats4<<<SB, 256>>>(cat, N, 64, 64);
    stats_final<<<1, 64>>>(N, 64, g5, b5);
    tapconv<27, 64, 32><<<GRID, 256>>>(cat, 64, nbr_fine, w_sub3,
                                       (float*)d_out, 32, 0, N, N);
}